// round 2
// baseline (speedup 1.0000x reference)
#include <cuda_runtime.h>
#include <stdint.h>

// Hash constants: ((c+1) * PIS[c]) for c = 0..7 (exact 64-bit products).
// tidx = (idx ^ PP[c]) & (TABLE_SIZE-1); valid since idx >= 0, TABLE_SIZE = 2^19.
__constant__ unsigned long long c_pp[8] = {
    774363409ull,      // 1 * 774363409
    5308871522ull,     // 2 * 2654435761
    2416379583ull,     // 3 * 805459861
    400000028ull,      // 4 * 100000007
    1671816955ull,     // 5 * 334363391
    8006180478ull,     // 6 * 1334363413
    5140543849ull,     // 7 * 734363407
    17074907144ull     // 8 * 2134363393
};

#define TABLE_MASK 0x7FFFFull
#define NRED 32

static __device__ int g_partial[NRED];

// ---------------------------------------------------------------------------
// Kernel 1: per-block max over depth -> g_partial[blockIdx]
// ---------------------------------------------------------------------------
__global__ void depth_reduce_kernel(const int* __restrict__ depth, int n) {
    int m = 0;
    for (int i = blockIdx.x * blockDim.x + threadIdx.x; i < n;
         i += gridDim.x * blockDim.x)
        m = max(m, depth[i]);
    #pragma unroll
    for (int s = 16; s > 0; s >>= 1)
        m = max(m, __shfl_xor_sync(0xffffffffu, m, s));
    __shared__ int sm[32];
    int w = threadIdx.x >> 5;
    if ((threadIdx.x & 31) == 0) sm[w] = m;
    __syncthreads();
    if (threadIdx.x == 0) {
        int nw = (blockDim.x + 31) >> 5;
        int mm = sm[0];
        for (int i = 1; i < nw; i++) mm = max(mm, sm[i]);
        g_partial[blockIdx.x] = mm;
    }
}

// ---------------------------------------------------------------------------
// Kernel 2: main encoding.
// Block = one ray (256 threads). Warp w = level l (0..7).
// Per warp: gather 8 corner feature rows (8 x 16 fp32 = 512B) into smem once,
// then each lane produces two float4 output slices (two points, same dim
// group) so both warp STG.128s are fully contiguous 512B stores.
// ---------------------------------------------------------------------------
__global__ void __launch_bounds__(256, 8) nbvh_main_kernel(
    const float* __restrict__ inp,          // [R,16,3]
    const int*   __restrict__ history,      // [R,64]  (int64 -> int32 in harness)
    const float* __restrict__ nodes_min,    // [N,3]
    const float* __restrict__ nodes_extent, // [N,3]
    const float* __restrict__ emb,          // [524288,16]
    float* __restrict__ out)                // [R, 8*16*16]
{
    __shared__ float4 sfeat[8][32];   // [warp][corner*4 + dim_group]
    __shared__ int s_activeL;

    const int tid  = threadIdx.x;
    const int w    = tid >> 5;       // level l
    const int lane = tid & 31;
    const int r    = blockIdx.x;

    if (tid == 0) {
        int m = 0;
        #pragma unroll
        for (int i = 0; i < NRED; i++) m = max(m, g_partial[i]);
        s_activeL = (m < 8) ? m : 8;
    }

    const int idx = history[r * 64 + w];

    // Gather features: lane -> (corner = lane>>2, float4 sub = lane&3)
    {
        const int c   = lane >> 2;
        const int sub = lane & 3;
        unsigned tix =
            (unsigned)(((unsigned long long)(unsigned)idx ^ c_pp[c]) & TABLE_MASK);
        sfeat[w][lane] =
            reinterpret_cast<const float4*>(emb)[(size_t)tix * 4 + sub];
    }

    // Node box (broadcast loads within warp; L1/L2 absorb duplicates)
    const float pmx = nodes_min[(size_t)idx * 3 + 0];
    const float pmy = nodes_min[(size_t)idx * 3 + 1];
    const float pmz = nodes_min[(size_t)idx * 3 + 2];
    const float rex = __fdividef(1.0f, nodes_extent[(size_t)idx * 3 + 0]);
    const float rey = __fdividef(1.0f, nodes_extent[(size_t)idx * 3 + 1]);
    const float rez = __fdividef(1.0f, nodes_extent[(size_t)idx * 3 + 2]);

    __syncthreads();   // sfeat + s_activeL visible

    const float act = (w < s_activeL) ? 1.0f : 0.0f;

    const int p_lo = lane >> 2;     // points p_lo and p_lo+8
    const int dsub = lane & 3;      // which float4 of the 16-dim feature
    const float* ib = inp + (size_t)r * 48;

    float wlo[8], whi[8];
    #pragma unroll
    for (int half = 0; half < 2; half++) {
        const int p = p_lo + half * 8;
        float x = fminf(fmaxf((ib[p * 3 + 0] - pmx) * rex, 0.0f), 1.0f);
        float y = fminf(fmaxf((ib[p * 3 + 1] - pmy) * rey, 0.0f), 1.0f);
        float z = fminf(fmaxf((ib[p * 3 + 2] - pmz) * rez, 0.0f), 1.0f);
        float ix = 1.0f - x, iy = 1.0f - y, iz = 1.0f - z;
        float* wv = half ? whi : wlo;
        wv[0] = ix * iy * iz;
        wv[1] =  x * iy * iz;
        wv[2] = ix *  y * iz;
        wv[3] = ix * iy *  z;
        wv[4] =  x * iy *  z;
        wv[5] = ix *  y *  z;
        wv[6] =  x *  y * iz;
        wv[7] =  x *  y *  z;
    }

    float4 alo = make_float4(0.f, 0.f, 0.f, 0.f);
    float4 ahi = make_float4(0.f, 0.f, 0.f, 0.f);
    #pragma unroll
    for (int c = 0; c < 8; c++) {
        const float4 f = sfeat[w][c * 4 + dsub];   // broadcast LDS.128
        alo.x = fmaf(wlo[c], f.x, alo.x);
        alo.y = fmaf(wlo[c], f.y, alo.y);
        alo.z = fmaf(wlo[c], f.z, alo.z);
        alo.w = fmaf(wlo[c], f.w, alo.w);
        ahi.x = fmaf(whi[c], f.x, ahi.x);
        ahi.y = fmaf(whi[c], f.y, ahi.y);
        ahi.z = fmaf(whi[c], f.z, ahi.z);
        ahi.w = fmaf(whi[c], f.w, ahi.w);
    }
    alo.x *= act; alo.y *= act; alo.z *= act; alo.w *= act;
    ahi.x *= act; ahi.y *= act; ahi.z *= act; ahi.w *= act;

    // Output tile for (r, l): 256 floats = 64 float4. Lane's slices at [lane]
    // and [32+lane] -> two fully contiguous 512B warp stores.
    float4* o = reinterpret_cast<float4*>(out) + ((size_t)r * 8 + w) * 64;
    o[lane]      = alo;
    o[32 + lane] = ahi;
}

// ---------------------------------------------------------------------------
extern "C" void kernel_launch(void* const* d_in, const int* in_sizes, int n_in,
                              void* d_out, int out_size) {
    const float* inp     = (const float*)d_in[0];
    const int*   history = (const int*)d_in[1];
    const int*   depth   = (const int*)d_in[2];
    const float* nmin    = (const float*)d_in[3];
    const float* next    = (const float*)d_in[4];
    const float* emb     = (const float*)d_in[5];
    float*       out     = (float*)d_out;

    const int R = in_sizes[2];   // number of rays (= depth element count)

    depth_reduce_kernel<<<NRED, 256>>>(depth, R);
    nbvh_main_kernel<<<R, 256>>>(inp, history, nmin, next, emb, out);
}